// round 17
// baseline (speedup 1.0000x reference)
#include <cuda_runtime.h>
#include <cuda_fp16.h>
#include <cstdint>

#define NGRAPH 16
#define NODESP 420
#define NN     6720
#define NP     6784    // padded to 53*128
#define NEDGE  53760
#define INDIM  2048
#define C1     2048
#define H1     1024
#define H2     64
#define OUTD   18
#define FCK    26880
#define NW1    8192    // 4 fused conv1 weight mats
#define NW2    256     // 4 fused conv2 weight mats
#define KTOT   2048

// ======================= device scratch =======================
__device__ float  g_q1f[(size_t)NP * 2048];   // conv1 q (fp32)
__device__ float  g_s1f[(size_t)NP * 2048];   // conv1 skip (fp32)
__device__ __half g_kv1h[(size_t)NP * 4096];  // conv1 k|v (fp16)
__device__ float g_al1[NEDGE * 2];            // per-edge exp (spill)
__device__ float g_c2[(size_t)NP * NW2];      // fused q|k|v|s conv2 out
__device__ float g_out2[(size_t)NN * H2];
__device__ float g_al2[NEDGE];
__device__ float g_f1[NGRAPH * 256];
__device__ int   g_src[NEDGE];
__device__ int   g_dst[NEDGE];
__device__ int   g_conn[NN];
__device__ int   g_ofs[NN + 1];
__device__ int   g_wofs[NN];
__device__ int   g_eidx[NEDGE];
__device__ __half g_a1[(size_t)NP * INDIM];   // A1 fp16
__device__ __half g_a2[(size_t)NP * C1];      // A2 fp16
__device__ __half g_w1t[(size_t)NW1 * INDIM]; // W1^T fp16 [n][k]
__device__ __half g_w2t[(size_t)NW2 * C1];
__device__ float g_bc1[NW1];
__device__ float g_bc2[NW2];

// ======================= sm_80-baseline PTX wrappers =======================
__device__ __forceinline__ uint32_t smem_u32(const void* p) {
    uint32_t a;
    asm("{ .reg .u64 t; cvta.to.shared.u64 t, %1; cvt.u32.u64 %0, t; }" : "=r"(a) : "l"(p));
    return a;
}
__device__ __forceinline__ void cpa16(uint32_t s, const void* g) {
    asm volatile("cp.async.cg.shared.global [%0], [%1], 16;" :: "r"(s), "l"(g));
}
__device__ __forceinline__ void cpa_commit() {
    asm volatile("cp.async.commit_group;" ::: "memory");
}
__device__ __forceinline__ void cpa_wait2() {
    asm volatile("cp.async.wait_group 2;" ::: "memory");
}
__device__ __forceinline__ void ldsm4(uint32_t* r, uint32_t addr) {
    asm volatile("ldmatrix.sync.aligned.m8n8.x4.shared.b16 {%0,%1,%2,%3}, [%4];"
        : "=r"(r[0]), "=r"(r[1]), "=r"(r[2]), "=r"(r[3]) : "r"(addr));
}
__device__ __forceinline__ void mma16816(float* d, const uint32_t* a, const uint32_t* b) {
    asm volatile("mma.sync.aligned.m16n8k16.row.col.f32.f16.f16.f32 "
        "{%0,%1,%2,%3}, {%4,%5,%6,%7}, {%8,%9}, {%0,%1,%2,%3};"
        : "+f"(d[0]), "+f"(d[1]), "+f"(d[2]), "+f"(d[3])
        : "r"(a[0]), "r"(a[1]), "r"(a[2]), "r"(a[3]), "r"(b[0]), "r"(b[1]));
}

// ===== launch 1: index normalization + init (g_f1 seeded with bias) =====
__global__ void k_cvt(const int* __restrict__ ei, const int* __restrict__ conn,
                      const float* __restrict__ bf1) {
    bool is64 = true;
#pragma unroll
    for (int i = 0; i < 16; i++)
        if (ei[2 * i + 1] != 0) is64 = false;
    int t = blockIdx.x * blockDim.x + threadIdx.x;
    int stride = gridDim.x * blockDim.x;
    if (is64) {
        for (int i = t; i < NEDGE; i += stride) { g_src[i] = ei[2 * i]; g_dst[i] = ei[2 * (NEDGE + i)]; }
        for (int i = t; i < NN; i += stride) g_conn[i] = conn[2 * i];
    } else {
        for (int i = t; i < NEDGE; i += stride) { g_src[i] = ei[i]; g_dst[i] = ei[NEDGE + i]; }
        for (int i = t; i < NN; i += stride) g_conn[i] = conn[i];
    }
    for (int i = t; i < NGRAPH * 256; i += stride) g_f1[i] = bf1[i & 255];
    // pad rows NN..NP of conv2 input must stay zero
    const __half z = __float2half(0.f);
    for (size_t j = (size_t)NN * C1 + t; j < (size_t)NP * C1; j += stride)
        g_a2[j] = z;
}

// ===== launch 2: smem histogram + scan -> CSR offsets =====
__global__ void k_scan() {
    __shared__ int scnt[NN];
    __shared__ int sh[1024];
    int t = threadIdx.x;
    for (int i = t; i < NN; i += 1024) scnt[i] = 0;
    __syncthreads();
    for (int e = t; e < NEDGE; e += 1024) atomicAdd(&scnt[g_dst[e]], 1);
    __syncthreads();
    int base = t * 7;
    int loc[7];
    int s = 0;
#pragma unroll
    for (int i = 0; i < 7; i++) {
        int n = base + i;
        int c = (n < NN) ? scnt[n] : 0;
        loc[i] = s;
        s += c;
    }
    sh[t] = s;
    __syncthreads();
    for (int off = 1; off < 1024; off <<= 1) {
        int v = (t >= off) ? sh[t - off] : 0;
        __syncthreads();
        sh[t] += v;
        __syncthreads();
    }
    int ex0 = sh[t] - s;
#pragma unroll
    for (int i = 0; i < 7; i++) {
        int n = base + i;
        if (n < NN) {
            g_ofs[n] = ex0 + loc[i];
            g_wofs[n] = ex0 + loc[i];
        }
    }
    if (t == 0) g_ofs[NN] = NEDGE;
}

// ===== launch 3: CSR fill + fused bias packing =====
__global__ void k_fillb(const float* b0, const float* b1, const float* b2, const float* b3,
                        const float* c0, const float* c1_, const float* c2, const float* c3) {
    int e = blockIdx.x * blockDim.x + threadIdx.x;
    if (e < NEDGE) {
        int pos = atomicAdd(&g_wofs[g_dst[e]], 1);
        g_eidx[pos] = e;
    }
    if (e < NW1) {
        int w = e >> 11, j = e & 2047;
        g_bc1[e] = (w == 0 ? b0 : w == 1 ? b1 : w == 2 ? b2 : b3)[j];
    }
    if (e < NW2) {
        int w = e >> 6, j = e & 63;
        g_bc2[e] = (w == 0 ? c0 : w == 1 ? c1_ : w == 2 ? c2 : c3)[j];
    }
}

// ===== launch 4: PE add -> fp16 A1 =====
__global__ void k_pe(const float* __restrict__ x, const float* __restrict__ npe,
                     const float* __restrict__ lpe, const float* __restrict__ gpe) {
    int node = blockIdx.x;
    __half* a1 = g_a1 + (size_t)node * INDIM;
    if (node >= NN) {
        for (int j = threadIdx.x; j < INDIM / 2; j += blockDim.x)
            ((uint32_t*)a1)[j] = 0u;
        return;
    }
    int lobe = g_conn[node] - 1;
    int lung = (lobe <= 1) ? 0 : 1;
    const float4* xp = (const float4*)(x + (size_t)node * INDIM);
    const float4* np = (const float4*)(npe + (size_t)(node % NODESP) * INDIM);
    const float4* lp = (const float4*)(lpe + (size_t)lobe * INDIM);
    const float4* gp = (const float4*)(gpe + (size_t)lung * INDIM);
    for (int j = threadIdx.x; j < INDIM / 4; j += blockDim.x) {
        float4 a = xp[j], b = np[j], c = lp[j], d = gp[j];
        float v[4] = { a.x + b.x + c.x + d.x, a.y + b.y + c.y + d.y,
                       a.z + b.z + c.z + d.z, a.w + b.w + c.w + d.w };
        ((__half2*)a1)[2 * j]     = __halves2half2(__float2half_rn(v[0]), __float2half_rn(v[1]));
        ((__half2*)a1)[2 * j + 1] = __halves2half2(__float2half_rn(v[2]), __float2half_rn(v[3]));
    }
}

// ===== launch 5: fused weight transpose -> fp16 (all 8 matrices) =====
__global__ void k_wsplit_all(const float* Wq1, const float* Wk1, const float* Wv1, const float* Ws1,
                             const float* Wq2, const float* Wk2, const float* Wv2, const float* Ws2) {
    __shared__ float tile[32][33];
    int z = blockIdx.z;
    const float* W;
    __half* T;
    int Nw, K, n0, noff;
    if (z < 4) {
        W = (z == 0) ? Wq1 : (z == 1) ? Wk1 : (z == 2) ? Wv1 : Ws1;
        T = g_w1t; Nw = C1; K = INDIM;
        n0 = blockIdx.x * 32; noff = z * 2048;
    } else {
        if (blockIdx.x >= 8) return;
        int mat = blockIdx.x >> 1;
        W = (mat == 0) ? Wq2 : (mat == 1) ? Wk2 : (mat == 2) ? Wv2 : Ws2;
        T = g_w2t; Nw = H2; K = C1;
        n0 = (blockIdx.x & 1) * 32; noff = mat * 64;
    }
    int k0 = blockIdx.y * 32;
    int tx = threadIdx.x, ty = threadIdx.y;  // 32 x 8
#pragma unroll
    for (int r = 0; r < 4; r++)
        tile[ty + r * 8][tx] = W[(size_t)(k0 + ty + r * 8) * Nw + n0 + tx];
    __syncthreads();
#pragma unroll
    for (int r = 0; r < 4; r++) {
        int n = n0 + ty + r * 8;
        T[(size_t)(noff + n) * K + k0 + tx] = __float2half_rn(tile[tx][ty + r * 8]);
    }
}

// ======================= mma.sync fp16 GEMM, BM=128 x BN=256, 512 thr =======================
// mode 0: C[m][n] = sum + bias[n] (fp32, ldc)
// mode 1: conv1 layout: cols [0,2048)->g_q1f fp32, [2048,6144)->g_kv1h fp16, [6144,8192)->g_s1f fp32
#define ASTAGE 16384
#define BSTAGE 32768
#define STAGE  (ASTAGE + BSTAGE)
#define GSMEM  (3 * STAGE)
#define NCHUNK (KTOT / 64)

__device__ __forceinline__ uint32_t swz(int row, int ch) {
    return (uint32_t)(row * 128 + ((ch ^ (row & 7)) << 4));
}

__device__ __forceinline__ void load_stage(uint32_t sbase, int tid, int s, int c,
        const __half* __restrict__ A, const __half* __restrict__ B, int m0, int n0) {
    uint32_t sa = sbase + s * STAGE;
    uint32_t sb = sa + ASTAGE;
    int k0 = c * 64;
#pragma unroll
    for (int i = 0; i < 2; i++) {
        int idx = tid + i * 512;          // 1024 ops: A rows 0..127, chunks 0..7
        int r = idx >> 3, ch = idx & 7;
        cpa16(sa + swz(r, ch), A + (size_t)(m0 + r) * KTOT + k0 + ch * 8);
    }
#pragma unroll
    for (int i = 0; i < 4; i++) {
        int idx = tid + i * 512;          // 2048 ops: B rows 0..255, chunks 0..7
        int r = idx >> 3, ch = idx & 7;
        cpa16(sb + swz(r, ch), B + (size_t)(n0 + r) * KTOT + k0 + ch * 8);
    }
    cpa_commit();
}

__global__ void __launch_bounds__(512, 1) mm_gemm(
        const __half* __restrict__ A, const __half* __restrict__ B,
        const float* __restrict__ bias, float* __restrict__ C, int ldc, int mode) {
    extern __shared__ char smem[];
    uint32_t sbase = smem_u32(smem);
    int tid = threadIdx.x, lane = tid & 31, wid = tid >> 5;
    int wm = wid >> 3, wn = wid & 7;      // 2(M) x 8(N), warp tile 64x32
    int m0 = blockIdx.y * 128, n0 = blockIdx.x * 256;

    float acc[4][4][4];
#pragma unroll
    for (int i = 0; i < 4; i++)
#pragma unroll
        for (int j = 0; j < 4; j++)
#pragma unroll
            for (int q = 0; q < 4; q++) acc[i][j][q] = 0.f;

    load_stage(sbase, tid, 0, 0, A, B, m0, n0);
    load_stage(sbase, tid, 1, 1, A, B, m0, n0);
    load_stage(sbase, tid, 2, 2, A, B, m0, n0);

    int a_row_l = (lane & 15);
    int a_chl   = (lane >> 4);
    int b_row_l = (lane & 7) + ((lane >> 4) << 3);
    int b_chl   = ((lane >> 3) & 1);

    for (int c = 0; c < NCHUNK; c++) {
        cpa_wait2();
        __syncthreads();
        uint32_t sa = sbase + (c % 3) * STAGE;
        uint32_t sb = sa + ASTAGE;
#pragma unroll
        for (int ks = 0; ks < 4; ks++) {
            uint32_t a_f[4][4], b_f[2][4];
#pragma unroll
            for (int mt = 0; mt < 4; mt++) {
                int row = wm * 64 + mt * 16 + a_row_l;
                ldsm4(a_f[mt], sa + swz(row, ks * 2 + a_chl));
            }
#pragma unroll
            for (int np = 0; np < 2; np++) {
                int row = wn * 32 + np * 16 + b_row_l;
                ldsm4(b_f[np], sb + swz(row, ks * 2 + b_chl));
            }
#pragma unroll
            for (int mt = 0; mt < 4; mt++)
#pragma unroll
                for (int nt = 0; nt < 4; nt++)
                    mma16816(acc[mt][nt], a_f[mt], &b_f[nt >> 1][(nt & 1) * 2]);
        }
        __syncthreads();
        if (c + 3 < NCHUNK)
            load_stage(sbase, tid, (c + 3) % 3, c + 3, A, B, m0, n0);
        else
            cpa_commit();
    }

#pragma unroll
    for (int mt = 0; mt < 4; mt++) {
        int row = m0 + wm * 64 + mt * 16 + (lane >> 2);
#pragma unroll
        for (int nt = 0; nt < 4; nt++) {
            int cg = n0 + wn * 32 + nt * 8 + (lane & 3) * 2;
            float b0 = bias[cg], b1 = bias[cg + 1];
            float v00 = acc[mt][nt][0] + b0, v01 = acc[mt][nt][1] + b1;
            float v10 = acc[mt][nt][2] + b0, v11 = acc[mt][nt][3] + b1;
            if (mode == 0) {
                float* p0 = C + (size_t)row * ldc + cg;
                p0[0] = v00; p0[1] = v01;
                float* p1 = p0 + 8 * ldc;
                p1[0] = v10; p1[1] = v11;
            } else if (cg < 2048) {
                float* p0 = g_q1f + (size_t)row * 2048 + cg;
                p0[0] = v00; p0[1] = v01;
                p0 += 8 * 2048;
                p0[0] = v10; p0[1] = v11;
            } else if (cg < 6144) {
                __half* p0 = g_kv1h + (size_t)row * 4096 + (cg - 2048);
                *(__half2*)p0 = __floats2half2_rn(v00, v01);
                *(__half2*)(p0 + 8 * 4096) = __floats2half2_rn(v10, v11);
            } else {
                float* p0 = g_s1f + (size_t)row * 2048 + (cg - 6144);
                p0[0] = v00; p0[1] = v01;
                p0 += 8 * 2048;
                p0[0] = v10; p0[1] = v11;
            }
        }
    }
}

// ======================= fused conv1 attention (CSR, no atomics) =======================
// q: g_q1f [node][2048] fp32; k|v: g_kv1h [node][4096] fp16 (k 0..2047, v 2048..4095);
// skip: g_s1f [node][2048] fp32. Thread t owns cols t*8..t*8+7 (head = t>>7).
__global__ void __launch_bounds__(256) k_att1() {
    __shared__ float s_part[32][8];
    __shared__ float s_den[2];
    int node = blockIdx.x;
    int tid = threadIdx.x, lane = tid & 31, wid = tid >> 5;
    int tcol = tid * 8;
    int head = tid >> 7;
    int ofs = g_ofs[node], nE = g_ofs[node + 1] - ofs;

    if (tid < 2) s_den[tid] = 0.f;

    float qreg[8];
    const float4* qp = (const float4*)(g_q1f + (size_t)node * 2048 + tcol);
    *(float4*)&qreg[0] = qp[0];
    *(float4*)&qreg[4] = qp[1];
    __syncthreads();

    for (int t0 = 0; t0 < nE; t0 += 32) {
        int tE = min(32, nE - t0);
        for (int e = 0; e < tE; e++) {
            int eid = g_eidx[ofs + t0 + e];
            int src = g_src[eid];
            union { uint4 u; __half2 h[4]; } K;
            K.u = *(const uint4*)(g_kv1h + (size_t)src * 4096 + tcol);
            float2 k0 = __half22float2(K.h[0]), k1 = __half22float2(K.h[1]);
            float2 k2 = __half22float2(K.h[2]), k3 = __half22float2(K.h[3]);
            float p = qreg[0] * k0.x + qreg[1] * k0.y + qreg[2] * k1.x + qreg[3] * k1.y
                    + qreg[4] * k2.x + qreg[5] * k2.y + qreg[6] * k3.x + qreg[7] * k3.y;
#pragma unroll
            for (int off = 16; off; off >>= 1) p += __shfl_xor_sync(0xffffffffu, p, off);
            if (lane == 0) s_part[e][wid] = p;
        }
        __syncthreads();
        if (tid < tE * 2) {
            int e = tid >> 1, h = tid & 1;
            float d = s_part[e][h * 4 + 0] + s_part[e][h * 4 + 1]
                    + s_part[e][h * 4 + 2] + s_part[e][h * 4 + 3];
            float ex = expf(d * (1.f / 32.f));   // softmax shift-invariant, alpha O(1)
            int eid = g_eidx[ofs + t0 + e];
            g_al1[eid * 2 + h] = ex;
            atomicAdd(&s_den[h], ex);
        }
        __syncthreads();
    }

    float invd = 1.f / (s_den[head] + 1e-16f);

    float acc[8] = {0.f, 0.f, 0.f, 0.f, 0.f, 0.f, 0.f, 0.f};
    for (int i = 0; i < nE; i++) {
        int eid = g_eidx[ofs + i];
        int src = g_src[eid];
        float a = g_al1[eid * 2 + head] * invd;
        union { uint4 u; __half2 h[4]; } V;
        V.u = *(const uint4*)(g_kv1h + (size_t)src * 4096 + 2048 + tcol);
        float2 v0 = __half22float2(V.h[0]), v1 = __half22float2(V.h[1]);
        float2 v2 = __half22float2(V.h[2]), v3 = __half22float2(V.h[3]);
        acc[0] += a * v0.x; acc[1] += a * v0.y; acc[2] += a * v1.x; acc[3] += a * v1.y;
        acc[4] += a * v2.x; acc[5] += a * v2.y; acc[6] += a * v3.x; acc[7] += a * v3.y;
    }

    const float4* sp = (const float4*)(g_s1f + (size_t)node * 2048 + tcol);
    float4 s0 = sp[0], s1 = sp[1];
    float skip[8] = {s0.x, s0.y, s0.z, s0.w, s1.x, s1.y, s1.z, s1.w};
    union { __half b[8]; uint4 u; } H;
#pragma unroll
    for (int j = 0; j < 8; j++)
        H.b[j] = __float2half_rn(fmaxf(acc[j] + skip[j], 0.f));
    *(uint4*)(g_a2 + (size_t)node * C1 + tcol) = H.u;
}

// ======================= fused conv2 attention (CSR, no atomics) =======================
__global__ void __launch_bounds__(64) k_att2() {
    __shared__ float s_part[32][2];
    __shared__ float s_den;
    int node = blockIdx.x;
    int tid = threadIdx.x, lane = tid & 31, wid = tid >> 5;
    int ofs = g_ofs[node], nE = g_ofs[node + 1] - ofs;

    if (tid == 0) s_den = 0.f;
    float qreg = g_c2[(size_t)node * NW2 + tid];
    __syncthreads();

    for (int t0 = 0; t0 < nE; t0 += 32) {
        int tE = min(32, nE - t0);
        for (int e = 0; e < tE; e++) {
            int eid = g_eidx[ofs + t0 + e];
            int src = g_src[eid];
            float p = qreg * g_c2[(size_t)src * NW2 + 64 + tid];
#pragma unroll
            for (int off = 16; off; off >>= 1) p += __shfl_xor_sync(0xffffffffu, p, off);
            if (lane == 0) s_part[e][wid] = p;
        }
        __syncthreads();
        if (tid < tE) {
            float d = s_part[tid][0] + s_part[tid][1];
            float ex = expf(d * 0.125f);
            g_al2[g_eidx[ofs + t0 + tid]] = ex;
            atomicAdd(&s_den, ex);
        }
        __syncthreads();
    }

    float invd = 1.f / (s_den + 1e-16f);
    float acc = 0.f;
    for (int i = 0; i < nE; i++) {
        int eid = g_eidx[ofs + i];
        int src = g_src[eid];
        acc += g_al2[eid] * invd * g_c2[(size_t)src * NW2 + 128 + tid];
    }
    float skip = g_c2[(size_t)node * NW2 + 192 + tid];
    g_out2[(size_t)node * H2 + tid] = fmaxf(acc + skip, 0.f);
}

// ======================= FC head =======================
// fc1: k-sliced, W read ONCE; partials accumulated into bias-seeded g_f1.
#define FSLICE 240
__global__ void __launch_bounds__(256) fc1s(const float* __restrict__ W) {
    __shared__ float a_s[FSLICE][17];   // pad 17 kills 16-way store conflict
    int k0 = blockIdx.x * FSLICE;
    int n = threadIdx.x;
    if (n < FSLICE) {
#pragma unroll
        for (int g = 0; g < NGRAPH; g++)
            a_s[n][g] = g_out2[(size_t)g * FCK + k0 + n];
    }
    __syncthreads();
    float acc[NGRAPH];
#pragma unroll
    for (int g = 0; g < NGRAPH; g++) acc[g] = 0.f;
    for (int k = 0; k < FSLICE; k++) {
        float w = W[(size_t)(k0 + k) * 256 + n];
#pragma unroll
        for (int g = 0; g < NGRAPH; g++)
            acc[g] = fmaf(a_s[k][g], w, acc[g]);
    }
#pragma unroll
    for (int g = 0; g < NGRAPH; g++)
        atomicAdd(&g_f1[g * 256 + n], acc[g]);
}

// fused fc2+fc3+fc4: one block per graph, 128 threads
__global__ void __launch_bounds__(128) k_fchead(
        const float* __restrict__ W2, const float* __restrict__ b2,
        const float* __restrict__ W3, const float* __restrict__ b3,
        const float* __restrict__ W4, const float* __restrict__ b4,
        float* __restrict__ out) {
    __shared__ float s1[256], s2[128], s3[64];
    int g = blockIdx.x, t = threadIdx.x;
    s1[t]       = fmaxf(g_f1[g * 256 + t], 0.f);
    s1[t + 128] = fmaxf(g_f1[g * 256 + t + 128], 0.f);
    __syncthreads();
    float a = b2[t];
    for (int k = 0; k < 256; k++) a = fmaf(s1[k], W2[(size_t)k * 128 + t], a);
    s2[t] = fmaxf(a, 0.f);
    __syncthreads();
    if (t < 64) {
        a = b3[t];
        for (int k = 0; k < 128; k++) a = fmaf(s2[k], W3[(size_t)k * 64 + t], a);
        s3[t] = fmaxf(a, 0.f);
    }
    __syncthreads();
    if (t < OUTD) {
        a = b4[t];
        for (int k = 0; k < 64; k++) a = fmaf(s3[k], W4[(size_t)k * OUTD + t], a);
        out[g * OUTD + t] = a;
    }
}

// ======================= launch =======================
extern "C" void kernel_launch(void* const* d_in, const int* in_sizes, int n_in,
                              void* d_out, int out_size) {
    const float* x = (const float*)d_in[0];
    const int* ei = (const int*)d_in[1];
    const int* conn = (const int*)d_in[2];
    const float* npe = (const float*)d_in[3];
    const float* lpe = (const float*)d_in[4];
    const float* gpe = (const float*)d_in[5];
    const float* Wq1 = (const float*)d_in[6];  const float* bq1 = (const float*)d_in[7];
    const float* Wk1 = (const float*)d_in[8];  const float* bk1 = (const float*)d_in[9];
    const float* Wv1 = (const float*)d_in[10]; const float* bv1 = (const float*)d_in[11];
    const float* Ws1 = (const float*)d_in[12]; const float* bs1 = (const float*)d_in[13];
    const float* Wq2 = (const float*)d_in[14]; const float* bq2 = (const float*)d_in[15];
    const float* Wk2 = (const float*)d_in[16]; const float* bk2 = (const float*)d_in[17];
    const float* Wv2 = (const float*)d_in[18]; const float* bv2 = (const float*)d_in[19];
    const float* Ws2 = (const float*)d_in[20]; const float* bs2 = (const float*)d_in[21];
    const float* Wf1 = (const float*)d_in[22]; const float* bf1 = (const float*)d_in[23];
    const float* Wf2 = (const float*)d_in[24]; const float* bf2 = (const float*)d_in[25];
    const float* Wf3 = (const float*)d_in[26]; const float* bf3 = (const float*)d_in[27];
    const float* Wf4 = (const float*)d_in[28]; const float* bf4 = (const float*)d_in[29];

    cudaFuncSetAttribute(mm_gemm, cudaFuncAttributeMaxDynamicSharedMemorySize, GSMEM);

    float *c2p, *f1p, *bc1p, *bc2p;
    __half *a1p, *a2p, *w1tp, *w2tp;
    cudaGetSymbolAddress((void**)&c2p, g_c2);
    cudaGetSymbolAddress((void**)&f1p, g_f1);
    cudaGetSymbolAddress((void**)&bc1p, g_bc1);
    cudaGetSymbolAddress((void**)&bc2p, g_bc2);
    cudaGetSymbolAddress((void**)&a1p, g_a1);
    cudaGetSymbolAddress((void**)&a2p, g_a2);
    cudaGetSymbolAddress((void**)&w1tp, g_w1t);
    cudaGetSymbolAddress((void**)&w2tp, g_w2t);

    k_cvt<<<256, 256>>>(ei, conn, bf1);
    k_scan<<<1, 1024>>>();
    k_fillb<<<(NEDGE + 255) / 256, 256>>>(bq1, bk1, bv1, bs1, bq2, bk2, bv2, bs2);
    k_pe<<<NP, 256>>>(x, npe, lpe, gpe);
    k_wsplit_all<<<dim3(64, 64, 5), dim3(32, 8)>>>(Wq1, Wk1, Wv1, Ws1, Wq2, Wk2, Wv2, Ws2);

    // conv1: fused 4-weight GEMM  [NP,2048] x [2048,8192], split-typed epilogue
    mm_gemm<<<dim3(NW1 / 256, NP / 128), 512, GSMEM>>>(a1p, w1tp, bc1p, (float*)0, 0, 1);

    k_att1<<<NN, 256>>>();

    // conv2: fused 4-weight GEMM  [NP,2048] x [2048,256]
    mm_gemm<<<dim3(NW2 / 256, NP / 128), 512, GSMEM>>>(a2p, w2tp, bc2p, c2p, NW2, 0);

    k_att2<<<NN, 64>>>();

    fc1s<<<FCK / FSLICE, 256>>>(Wf1);
    k_fchead<<<NGRAPH, 128>>>(Wf2, bf2, Wf3, bf3, Wf4, bf4, (float*)d_out);
}